// round 5
// baseline (speedup 1.0000x reference)
#include <cuda_runtime.h>
#include <cstdint>
#include <math.h>

#define N_Q      4096
#define N_KV     32768
#define C_DIM    256
#define KNN      100
#define THREADS  256
#define LN_EPS   1e-5f
#define NWORDS   (N_KV / 2)      // 16384 packed 2x16-bit key words
#define CAND_CAP 1024
#define QSCALE   2048.0f         // linear d2 -> key16 quantization

struct __align__(16) SmemLayout {
    unsigned int keyw[NWORDS];          // 65536 B
    unsigned int cand[CAND_CAP];        // 4096 B: (lowbyte<<16) | idx
    unsigned int hist[256];
    float        qs[C_DIM];
    float        logits[128];
    float        wts[128];
    int          sel[128];
    int          eq_idx[64];
    float        eq_d2[64];
    int          wsum[8];
    float        red1[8];
    float        red2[8];
    unsigned int bsel;
    int          krem_s;
    int          n_less;
    int          eq_ctr;
    int          cand_ctr;
    float        sm_max, sm_sum, sm_mean, sm_rstd;
};

extern __shared__ unsigned char smem_raw[];

// Parallel 256-bin rank-select: finds bin b whose cumulative count crosses krem.
// Sets s.bsel = b, s.krem_s = krem - exclusive_prefix(b). All-thread collective.
__device__ __forceinline__ void bin_select(SmemLayout& s, int krem,
                                           int tid, int lane, int wid)
{
    int c = (int)s.hist[tid];
    int x = c;
    #pragma unroll
    for (int o = 1; o < 32; o <<= 1) {
        int y = __shfl_up_sync(0xffffffffu, x, o);
        if (lane >= o) x += y;
    }
    if (lane == 31) s.wsum[wid] = x;
    __syncthreads();
    if (tid == 0) {
        int acc = 0;
        #pragma unroll
        for (int ww = 0; ww < 8; ww++) { int t = s.wsum[ww]; s.wsum[ww] = acc; acc += t; }
    }
    __syncthreads();
    int incl = x + s.wsum[wid];
    int excl = incl - c;
    if (krem > excl && krem <= incl) { s.bsel = (unsigned)tid; s.krem_s = krem - excl; }
    __syncthreads();
}

__device__ __forceinline__ unsigned quant_key(float d2)
{
    float f = fmaxf(d2, 0.0f) * QSCALE;
    unsigned k = (unsigned)f;                 // round toward zero, monotone
    return k > 65535u ? 65535u : k;
}

__global__ __launch_bounds__(THREADS)
void sparse_attn_kernel(const float* __restrict__ q_feat,
                        const float* __restrict__ k_feat,
                        const float* __restrict__ v_feat,
                        const float* __restrict__ q_pos,
                        const float* __restrict__ k_pos,
                        const float* __restrict__ gamma,
                        const float* __restrict__ beta,
                        float* __restrict__ out)
{
    SmemLayout& s = *reinterpret_cast<SmemLayout*>(smem_raw);
    const int i    = blockIdx.x;
    const int tid  = threadIdx.x;
    const int lane = tid & 31;
    const int wid  = tid >> 5;

    const float qx = q_pos[i * 3 + 0];
    const float qy = q_pos[i * 3 + 1];
    const float qz = q_pos[i * 3 + 2];
    const float sq = qx * qx + qy * qy + qz * qz;

    // ---- Phase 1: distances -> 16-bit linear keys + hi-byte histogram ----
    s.hist[tid] = 0u;
    if (tid == 0) { s.n_less = 0; s.eq_ctr = 0; s.cand_ctr = 0; }
    __syncthreads();

    const float2* kp2 = reinterpret_cast<const float2*>(k_pos);
    #pragma unroll 1
    for (int w = tid; w < NWORDS; w += 2 * THREADS) {
        const int w2 = w + THREADS;
        // front-batch all six 64-bit loads for MLP
        float2 p0 = kp2[3 * w + 0];
        float2 p1 = kp2[3 * w + 1];
        float2 p2 = kp2[3 * w + 2];
        float2 p3 = kp2[3 * w2 + 0];
        float2 p4 = kp2[3 * w2 + 1];
        float2 p5 = kp2[3 * w2 + 2];

        float ax = p0.x, ay = p0.y, az = p1.x;
        float bx = p1.y, by = p2.x, bz = p2.y;
        float cx = p3.x, cy = p3.y, cz = p4.x;
        float dx = p4.y, dy = p5.x, dz = p5.y;

        float d2a = (sq + ax * ax + ay * ay + az * az)
                  - 2.0f * (qx * ax + qy * ay + qz * az);
        float d2b = (sq + bx * bx + by * by + bz * bz)
                  - 2.0f * (qx * bx + qy * by + qz * bz);
        float d2c = (sq + cx * cx + cy * cy + cz * cz)
                  - 2.0f * (qx * cx + qy * cy + qz * cz);
        float d2d = (sq + dx * dx + dy * dy + dz * dz)
                  - 2.0f * (qx * dx + qy * dy + qz * dz);

        unsigned ka = quant_key(d2a), kb = quant_key(d2b);
        unsigned kc = quant_key(d2c), kd = quant_key(d2d);
        s.keyw[w]  = ka | (kb << 16);
        s.keyw[w2] = kc | (kd << 16);
        atomicAdd(&s.hist[ka >> 8], 1u);
        atomicAdd(&s.hist[kb >> 8], 1u);
        atomicAdd(&s.hist[kc >> 8], 1u);
        atomicAdd(&s.hist[kd >> 8], 1u);
    }
    __syncthreads();

    bin_select(s, KNN, tid, lane, wid);
    const unsigned hb = s.bsel;
    const int krem = s.krem_s;
    __syncthreads();
    s.hist[tid] = 0u;
    __syncthreads();

    // ---- Pass B: one keyw scan; hi<hb -> sel, hi==hb -> candidate buffer ----
    for (int w = tid; w < NWORDS; w += THREADS) {
        unsigned word = s.keyw[w];
        unsigned ka = word & 0xffffu, kb = word >> 16;
        unsigned ba = ka >> 8, bb = kb >> 8;
        if (ba < hb) {
            s.sel[atomicAdd(&s.n_less, 1)] = 2 * w;
        } else if (ba == hb) {
            int p = atomicAdd(&s.cand_ctr, 1);
            if (p < CAND_CAP) s.cand[p] = ((ka & 255u) << 16) | (unsigned)(2 * w);
        }
        if (bb < hb) {
            s.sel[atomicAdd(&s.n_less, 1)] = 2 * w + 1;
        } else if (bb == hb) {
            int p = atomicAdd(&s.cand_ctr, 1);
            if (p < CAND_CAP) s.cand[p] = ((kb & 255u) << 16) | (unsigned)(2 * w + 1);
        }
    }
    __syncthreads();

    const int nc = s.cand_ctr;
    int need_eq;
    if (nc <= CAND_CAP) {
        // ---- Small path: low-byte select over compacted candidates ----
        for (int t = tid; t < nc; t += THREADS)
            atomicAdd(&s.hist[s.cand[t] >> 16], 1u);
        __syncthreads();
        bin_select(s, krem, tid, lane, wid);
        const unsigned lbsel = s.bsel;
        need_eq = s.krem_s;
        __syncthreads();
        for (int t = tid; t < nc; t += THREADS) {
            unsigned cw = s.cand[t];
            unsigned lb = cw >> 16;
            int j = (int)(cw & 0xffffu);
            if (lb < lbsel) {
                s.sel[atomicAdd(&s.n_less, 1)] = j;
            } else if (lb == lbsel) {
                int p = atomicAdd(&s.eq_ctr, 1);
                if (p < 64) s.eq_idx[p] = j;
            }
        }
        __syncthreads();
    } else {
        // ---- Fallback: full-scan low-byte hist + collection ----
        for (int w = tid; w < NWORDS; w += THREADS) {
            unsigned word = s.keyw[w];
            unsigned ka = word & 0xffffu, kb = word >> 16;
            if ((ka >> 8) == hb) atomicAdd(&s.hist[ka & 255u], 1u);
            if ((kb >> 8) == hb) atomicAdd(&s.hist[kb & 255u], 1u);
        }
        __syncthreads();
        bin_select(s, krem, tid, lane, wid);
        const unsigned lbsel = s.bsel;
        need_eq = s.krem_s;
        __syncthreads();
        for (int w = tid; w < NWORDS; w += THREADS) {
            unsigned word = s.keyw[w];
            unsigned ka = word & 0xffffu, kb = word >> 16;
            if ((ka >> 8) == hb) {
                unsigned lb = ka & 255u;
                if (lb < lbsel) s.sel[atomicAdd(&s.n_less, 1)] = 2 * w;
                else if (lb == lbsel) {
                    int p = atomicAdd(&s.eq_ctr, 1);
                    if (p < 64) s.eq_idx[p] = 2 * w;
                }
            }
            if ((kb >> 8) == hb) {
                unsigned lb = kb & 255u;
                if (lb < lbsel) s.sel[atomicAdd(&s.n_less, 1)] = 2 * w + 1;
                else if (lb == lbsel) {
                    int p = atomicAdd(&s.eq_ctr, 1);
                    if (p < 64) s.eq_idx[p] = 2 * w + 1;
                }
            }
        }
        __syncthreads();
    }

    // ---- Tie resolution at full fp32 precision (tiny candidate set) ----
    int ne = s.eq_ctr; if (ne > 64) ne = 64;
    if (tid < ne) {
        int j = s.eq_idx[tid];
        float kx = k_pos[3 * j], ky = k_pos[3 * j + 1], kz = k_pos[3 * j + 2];
        float d2 = sq + kx * kx + ky * ky + kz * kz
                 - 2.0f * (qx * kx + qy * ky + qz * kz);
        s.eq_d2[tid] = fmaxf(d2, 0.0f);
    }
    __syncthreads();
    if (tid == 0) {
        int nl = s.n_less;
        int take = need_eq < ne ? need_eq : ne;
        for (int a = 0; a < take; ++a) {
            int best = a;
            for (int b = a + 1; b < ne; ++b) {
                if (s.eq_d2[b] < s.eq_d2[best] ||
                    (s.eq_d2[b] == s.eq_d2[best] && s.eq_idx[b] < s.eq_idx[best]))
                    best = b;
            }
            float td = s.eq_d2[a]; s.eq_d2[a] = s.eq_d2[best]; s.eq_d2[best] = td;
            int   ti = s.eq_idx[a]; s.eq_idx[a] = s.eq_idx[best]; s.eq_idx[best] = ti;
            s.sel[nl + a] = s.eq_idx[a];
        }
    }
    __syncthreads();

    // ---- Phase 4: attention logits (warp per logit, float4) ----
    s.qs[tid] = q_feat[(size_t)i * C_DIM + tid];
    __syncthreads();
    const float4* qs4 = reinterpret_cast<const float4*>(s.qs);

    for (int j = wid; j < KNN; j += 8) {
        const float4* kr = reinterpret_cast<const float4*>(
            k_feat + (size_t)s.sel[j] * C_DIM);
        float4 a0 = kr[lane],  a1 = kr[lane + 32];
        float4 b0 = qs4[lane], b1 = qs4[lane + 32];
        float p = a0.x * b0.x + a0.y * b0.y + a0.z * b0.z + a0.w * b0.w
                + a1.x * b1.x + a1.y * b1.y + a1.z * b1.z + a1.w * b1.w;
        #pragma unroll
        for (int o = 16; o > 0; o >>= 1)
            p += __shfl_xor_sync(0xffffffffu, p, o);
        if (lane == 0) s.logits[j] = p * 0.0625f;   // C^-0.5 = 1/16
    }
    __syncthreads();

    // ---- Phase 5: softmax over 100 logits ----
    if (wid == 0) {
        float m = -INFINITY;
        #pragma unroll
        for (int u = 0; u < 4; u++) {
            int j = lane + 32 * u;
            if (j < KNN) m = fmaxf(m, s.logits[j]);
        }
        #pragma unroll
        for (int o = 16; o > 0; o >>= 1)
            m = fmaxf(m, __shfl_xor_sync(0xffffffffu, m, o));
        float ssum = 0.0f;
        #pragma unroll
        for (int u = 0; u < 4; u++) {
            int j = lane + 32 * u;
            if (j < KNN) ssum += expf(s.logits[j] - m);
        }
        #pragma unroll
        for (int o = 16; o > 0; o >>= 1)
            ssum += __shfl_xor_sync(0xffffffffu, ssum, o);
        if (lane == 0) { s.sm_max = m; s.sm_sum = ssum; }
    }
    __syncthreads();
    if (tid < KNN)
        s.wts[tid] = expf(s.logits[tid] - s.sm_max) / s.sm_sum;
    __syncthreads();

    // ---- Phase 6: weighted V gather (thread t owns channel t) ----
    float acc = 0.0f;
    #pragma unroll 10
    for (int j = 0; j < KNN; j++)
        acc += s.wts[j] * v_feat[(size_t)s.sel[j] * C_DIM + tid];

    // res.at[arange].set(x) covers every row -> y = x + x = 2x
    float y = 2.0f * acc;

    // ---- Phase 7: LayerNorm over C=256 ----
    float s1 = y, s2 = y * y;
    #pragma unroll
    for (int o = 16; o > 0; o >>= 1) {
        s1 += __shfl_xor_sync(0xffffffffu, s1, o);
        s2 += __shfl_xor_sync(0xffffffffu, s2, o);
    }
    if (lane == 0) { s.red1[wid] = s1; s.red2[wid] = s2; }
    __syncthreads();
    if (wid == 0) {
        float a = (lane < 8) ? s.red1[lane] : 0.0f;
        float b = (lane < 8) ? s.red2[lane] : 0.0f;
        #pragma unroll
        for (int o = 4; o > 0; o >>= 1) {
            a += __shfl_xor_sync(0xffffffffu, a, o);
            b += __shfl_xor_sync(0xffffffffu, b, o);
        }
        if (lane == 0) {
            float mean = a * (1.0f / C_DIM);
            float var  = b * (1.0f / C_DIM) - mean * mean;
            s.sm_mean = mean;
            s.sm_rstd = rsqrtf(var + LN_EPS);
        }
    }
    __syncthreads();

    out[(size_t)i * C_DIM + tid] =
        (y - s.sm_mean) * s.sm_rstd * gamma[tid] + beta[tid];
}

extern "C" void kernel_launch(void* const* d_in, const int* in_sizes, int n_in,
                              void* d_out, int out_size)
{
    // inputs: 0=res_feat (dead: scatter covers all rows), 1=q_feat, 2=k_feat,
    //         3=v_feat, 4=q_pos, 5=k_pos, 6=gamma, 7=beta
    const float* q_feat = (const float*)d_in[1];
    const float* k_feat = (const float*)d_in[2];
    const float* v_feat = (const float*)d_in[3];
    const float* q_pos  = (const float*)d_in[4];
    const float* k_pos  = (const float*)d_in[5];
    const float* gamma  = (const float*)d_in[6];
    const float* beta   = (const float*)d_in[7];
    float* out = (float*)d_out;

    const int smem_bytes = (int)sizeof(SmemLayout);
    cudaFuncSetAttribute(sparse_attn_kernel,
                         cudaFuncAttributeMaxDynamicSharedMemorySize, smem_bytes);
    sparse_attn_kernel<<<N_Q, THREADS, smem_bytes>>>(
        q_feat, k_feat, v_feat, q_pos, k_pos, gamma, beta, out);
}

// round 7
// speedup vs baseline: 1.8884x; 1.8884x over previous
#include <cuda_runtime.h>
#include <cstdint>
#include <math.h>

#define N_Q      4096
#define N_KV     32768
#define C_DIM    256
#define KNN      100
#define THREADS  256
#define MQ       4                 // queries per CTA
#define GRID     (N_Q / MQ)
#define LN_EPS   1e-5f
#define NWORDS   (N_KV / 2)        // 16384 point-pairs
#define CAND_CAP 2048
#define QSCALE   2048.0f
#define SRANK    20                // sample rank for threshold (of 1024 samples)

struct __align__(16) SmemLayout {
    unsigned int cand[MQ][CAND_CAP];   // 32768 B: (key16<<16) | idx
    __align__(16) float qs[C_DIM];     // float4-accessed: MUST be 16B aligned
    int          candn[MQ];
    float        thi[MQ];
    int          qflag[MQ];
    int          redo;
    unsigned int hist[256];
    int          wsum[8];
    unsigned int bsel;
    int          krem_s;
    float        qpos[MQ][4];          // qx,qy,qz,|q|^2
    float        logits[128];
    float        wts[128];
    int          sel[128];
    int          eq_idx[64];
    float        eq_d2[64];
    int          n_less;
    int          eq_ctr;
    float        red1[8];
    float        red2[8];
    float        sm_max, sm_sum, sm_mean, sm_rstd;
};

extern __shared__ unsigned char smem_raw[];

// Parallel 256-bin rank-select: finds bin whose cumulative count crosses krem.
// Sets s.bsel = bin, s.krem_s = krem - exclusive_prefix(bin). Block collective.
__device__ __forceinline__ void bin_select(SmemLayout& s, int krem,
                                           int tid, int lane, int wid)
{
    int c = (int)s.hist[tid];
    int x = c;
    #pragma unroll
    for (int o = 1; o < 32; o <<= 1) {
        int y = __shfl_up_sync(0xffffffffu, x, o);
        if (lane >= o) x += y;
    }
    if (lane == 31) s.wsum[wid] = x;
    __syncthreads();
    if (tid == 0) {
        int acc = 0;
        #pragma unroll
        for (int ww = 0; ww < 8; ww++) { int t = s.wsum[ww]; s.wsum[ww] = acc; acc += t; }
    }
    __syncthreads();
    int incl = x + s.wsum[wid];
    int excl = incl - c;
    if (krem > excl && krem <= incl) { s.bsel = (unsigned)tid; s.krem_s = krem - excl; }
    __syncthreads();
}

__device__ __forceinline__ unsigned quant_key(float d2)
{
    float f = fmaxf(d2, 0.0f) * QSCALE;
    unsigned k = (unsigned)f;
    return k > 65535u ? 65535u : k;
}

__global__ __launch_bounds__(THREADS)
void sparse_attn_kernel(const float* __restrict__ q_feat,
                        const float* __restrict__ k_feat,
                        const float* __restrict__ v_feat,
                        const float* __restrict__ q_pos,
                        const float* __restrict__ k_pos,
                        const float* __restrict__ gamma,
                        const float* __restrict__ beta,
                        float* __restrict__ out)
{
    SmemLayout& s = *reinterpret_cast<SmemLayout*>(smem_raw);
    const int tid   = threadIdx.x;
    const int lane  = tid & 31;
    const int wid   = tid >> 5;
    const int qbase = blockIdx.x * MQ;

    if (tid < MQ) {
        float x = q_pos[(qbase + tid) * 3 + 0];
        float y = q_pos[(qbase + tid) * 3 + 1];
        float z = q_pos[(qbase + tid) * 3 + 2];
        s.qpos[tid][0] = x; s.qpos[tid][1] = y; s.qpos[tid][2] = z;
        s.qpos[tid][3] = x * x + y * y + z * z;
        s.candn[tid] = 0; s.qflag[tid] = 1;
    }
    __syncthreads();

    float Qx[MQ], Qy[MQ], Qz[MQ], Qs[MQ];
    #pragma unroll
    for (int m = 0; m < MQ; m++) {
        Qx[m] = s.qpos[m][0]; Qy[m] = s.qpos[m][1];
        Qz[m] = s.qpos[m][2]; Qs[m] = s.qpos[m][3];
    }

    // ---- Sample pass: per-query threshold from a 1/32 stride sample ----
    float sx[4], sy[4], sz[4];
    #pragma unroll
    for (int k = 0; k < 4; k++) {
        int j = 32 * (tid + 256 * k);
        sx[k] = k_pos[3 * j + 0];
        sy[k] = k_pos[3 * j + 1];
        sz[k] = k_pos[3 * j + 2];
    }
    for (int m = 0; m < MQ; m++) {
        s.hist[tid] = 0u;
        __syncthreads();
        #pragma unroll
        for (int k = 0; k < 4; k++) {
            float d2 = Qs[m] + sx[k] * sx[k] + sy[k] * sy[k] + sz[k] * sz[k]
                     - 2.0f * (Qx[m] * sx[k] + Qy[m] * sy[k] + Qz[m] * sz[k]);
            atomicAdd(&s.hist[quant_key(d2) >> 8], 1u);
        }
        __syncthreads();
        bin_select(s, SRANK, tid, lane, wid);
        if (tid == 0)
            s.thi[m] = (float)((s.bsel + 1u) << 8) * (1.0f / QSCALE);
        __syncthreads();
    }

    bool active[MQ];
    float Thi[MQ];
    #pragma unroll
    for (int m = 0; m < MQ; m++) { active[m] = true; Thi[m] = s.thi[m]; }

    // ---- Main pass: stream k_pos once, compact candidates per query ----
    const float2* kp2 = reinterpret_cast<const float2*>(k_pos);
    for (int attempt = 0; attempt < 6; attempt++) {
        for (int w = tid; w < NWORDS; w += THREADS) {
            float2 p0 = kp2[3 * w + 0];
            float2 p1 = kp2[3 * w + 1];
            float2 p2 = kp2[3 * w + 2];
            float ax = p0.x, ay = p0.y, az = p1.x;
            float bx = p1.y, by = p2.x, bz = p2.y;
            float kka = ax * ax + ay * ay + az * az;
            float kkb = bx * bx + by * by + bz * bz;
            #pragma unroll
            for (int m = 0; m < MQ; m++) {
                if (!active[m]) continue;
                float d2a = Qs[m] + kka
                          - 2.0f * (Qx[m] * ax + Qy[m] * ay + Qz[m] * az);
                float d2b = Qs[m] + kkb
                          - 2.0f * (Qx[m] * bx + Qy[m] * by + Qz[m] * bz);
                if (d2a < Thi[m]) {
                    int p = atomicAdd(&s.candn[m], 1);
                    if (p < CAND_CAP)
                        s.cand[m][p] = (quant_key(d2a) << 16) | (unsigned)(2 * w);
                }
                if (d2b < Thi[m]) {
                    int p = atomicAdd(&s.candn[m], 1);
                    if (p < CAND_CAP)
                        s.cand[m][p] = (quant_key(d2b) << 16) | (unsigned)(2 * w + 1);
                }
            }
        }
        __syncthreads();
        if (tid == 0) s.redo = 0;
        __syncthreads();
        if (tid < MQ && s.qflag[tid]) {
            int n = s.candn[tid];
            if (n >= KNN && n <= CAND_CAP) {
                s.qflag[tid] = 0;
            } else {
                s.candn[tid] = 0;
                s.thi[tid] = (n < KNN) ? s.thi[tid] * 2.0f : s.thi[tid] * 0.5f;
                atomicExch(&s.redo, 1);
            }
        }
        __syncthreads();
        if (!s.redo) break;
        #pragma unroll
        for (int m = 0; m < MQ; m++) {
            active[m] = s.qflag[m] != 0;
            Thi[m] = s.thi[m];
        }
        __syncthreads();
    }

    // ---- Per query: exact selection + attention + LayerNorm ----
    for (int m = 0; m < MQ; m++) {
        const int qi = qbase + m;
        const int nc_raw = s.candn[m];
        const int nc = nc_raw < CAND_CAP ? nc_raw : CAND_CAP;

        // dynamic shift so candidate keys fit 256 bins
        int maxkey = (int)(s.thi[m] * QSCALE);
        if (maxkey > 65535) maxkey = 65535;
        int sh = 0;
        while ((maxkey >> sh) > 255) sh++;

        s.hist[tid] = 0u;
        if (tid == 0) { s.n_less = 0; s.eq_ctr = 0; }
        __syncthreads();
        for (int t = tid; t < nc; t += THREADS)
            atomicAdd(&s.hist[(s.cand[m][t] >> 16) >> sh], 1u);
        __syncthreads();
        bin_select(s, KNN, tid, lane, wid);
        const unsigned bsel = s.bsel;
        const int need_eq = s.krem_s;
        __syncthreads();
        for (int t = tid; t < nc; t += THREADS) {
            unsigned cw = s.cand[m][t];
            unsigned b = (cw >> 16) >> sh;
            int j = (int)(cw & 0xffffu);
            if (b < bsel) {
                s.sel[atomicAdd(&s.n_less, 1)] = j;
            } else if (b == bsel) {
                int p = atomicAdd(&s.eq_ctr, 1);
                if (p < 64) s.eq_idx[p] = j;
            }
        }
        __syncthreads();

        // exact fp32 resolution of the boundary bin
        int ne = s.eq_ctr; if (ne > 64) ne = 64;
        if (tid < ne) {
            int j = s.eq_idx[tid];
            float kx = k_pos[3 * j], ky = k_pos[3 * j + 1], kz = k_pos[3 * j + 2];
            float d2 = Qs[m] + kx * kx + ky * ky + kz * kz
                     - 2.0f * (Qx[m] * kx + Qy[m] * ky + Qz[m] * kz);
            s.eq_d2[tid] = fmaxf(d2, 0.0f);
        }
        __syncthreads();
        if (tid == 0) {
            int nl = s.n_less;
            int take = need_eq < ne ? need_eq : ne;
            for (int a = 0; a < take; ++a) {
                int best = a;
                for (int b = a + 1; b < ne; ++b) {
                    if (s.eq_d2[b] < s.eq_d2[best] ||
                        (s.eq_d2[b] == s.eq_d2[best] && s.eq_idx[b] < s.eq_idx[best]))
                        best = b;
                }
                float td = s.eq_d2[a]; s.eq_d2[a] = s.eq_d2[best]; s.eq_d2[best] = td;
                int   ti = s.eq_idx[a]; s.eq_idx[a] = s.eq_idx[best]; s.eq_idx[best] = ti;
                s.sel[nl + a] = s.eq_idx[a];
            }
        }

        // ---- attention logits (warp per logit, float4) ----
        s.qs[tid] = q_feat[(size_t)qi * C_DIM + tid];
        __syncthreads();
        const float4* qs4 = reinterpret_cast<const float4*>(s.qs);

        for (int j = wid; j < KNN; j += 8) {
            const float4* kr = reinterpret_cast<const float4*>(
                k_feat + (size_t)s.sel[j] * C_DIM);
            float4 a0 = kr[lane],  a1 = kr[lane + 32];
            float4 b0 = qs4[lane], b1 = qs4[lane + 32];
            float p = a0.x * b0.x + a0.y * b0.y + a0.z * b0.z + a0.w * b0.w
                    + a1.x * b1.x + a1.y * b1.y + a1.z * b1.z + a1.w * b1.w;
            #pragma unroll
            for (int o = 16; o > 0; o >>= 1)
                p += __shfl_xor_sync(0xffffffffu, p, o);
            if (lane == 0) s.logits[j] = p * 0.0625f;   // C^-0.5 = 1/16
        }
        __syncthreads();

        // ---- softmax over 100 logits ----
        if (wid == 0) {
            float mx = -INFINITY;
            #pragma unroll
            for (int u = 0; u < 4; u++) {
                int j = lane + 32 * u;
                if (j < KNN) mx = fmaxf(mx, s.logits[j]);
            }
            #pragma unroll
            for (int o = 16; o > 0; o >>= 1)
                mx = fmaxf(mx, __shfl_xor_sync(0xffffffffu, mx, o));
            float ssum = 0.0f;
            #pragma unroll
            for (int u = 0; u < 4; u++) {
                int j = lane + 32 * u;
                if (j < KNN) ssum += expf(s.logits[j] - mx);
            }
            #pragma unroll
            for (int o = 16; o > 0; o >>= 1)
                ssum += __shfl_xor_sync(0xffffffffu, ssum, o);
            if (lane == 0) { s.sm_max = mx; s.sm_sum = ssum; }
        }
        __syncthreads();
        if (tid < KNN)
            s.wts[tid] = expf(s.logits[tid] - s.sm_max) / s.sm_sum;
        __syncthreads();

        // ---- weighted V gather (thread t owns channel t) ----
        float acc = 0.0f;
        #pragma unroll 10
        for (int j = 0; j < KNN; j++)
            acc += s.wts[j] * v_feat[(size_t)s.sel[j] * C_DIM + tid];

        // res.at[arange].set(x) covers every row -> y = x + x = 2x
        float y = 2.0f * acc;

        // ---- LayerNorm over C=256 ----
        float s1 = y, s2 = y * y;
        #pragma unroll
        for (int o = 16; o > 0; o >>= 1) {
            s1 += __shfl_xor_sync(0xffffffffu, s1, o);
            s2 += __shfl_xor_sync(0xffffffffu, s2, o);
        }
        if (lane == 0) { s.red1[wid] = s1; s.red2[wid] = s2; }
        __syncthreads();
        if (wid == 0) {
            float a = (lane < 8) ? s.red1[lane] : 0.0f;
            float b = (lane < 8) ? s.red2[lane] : 0.0f;
            #pragma unroll
            for (int o = 4; o > 0; o >>= 1) {
                a += __shfl_xor_sync(0xffffffffu, a, o);
                b += __shfl_xor_sync(0xffffffffu, b, o);
            }
            if (lane == 0) {
                float mean = a * (1.0f / C_DIM);
                float var  = b * (1.0f / C_DIM) - mean * mean;
                s.sm_mean = mean;
                s.sm_rstd = rsqrtf(var + LN_EPS);
            }
        }
        __syncthreads();

        out[(size_t)qi * C_DIM + tid] =
            (y - s.sm_mean) * s.sm_rstd * gamma[tid] + beta[tid];
        __syncthreads();
    }
}

extern "C" void kernel_launch(void* const* d_in, const int* in_sizes, int n_in,
                              void* d_out, int out_size)
{
    // inputs: 0=res_feat (dead: scatter covers all rows), 1=q_feat, 2=k_feat,
    //         3=v_feat, 4=q_pos, 5=k_pos, 6=gamma, 7=beta
    const float* q_feat = (const float*)d_in[1];
    const float* k_feat = (const float*)d_in[2];
    const float* v_feat = (const float*)d_in[3];
    const float* q_pos  = (const float*)d_in[4];
    const float* k_pos  = (const float*)d_in[5];
    const float* gamma  = (const float*)d_in[6];
    const float* beta   = (const float*)d_in[7];
    float* out = (float*)d_out;

    const int smem_bytes = (int)sizeof(SmemLayout);
    cudaFuncSetAttribute(sparse_attn_kernel,
                         cudaFuncAttributeMaxDynamicSharedMemorySize, smem_bytes);
    sparse_attn_kernel<<<GRID, THREADS, smem_bytes>>>(
        q_feat, k_feat, v_feat, q_pos, k_pos, gamma, beta, out);
}

// round 9
// speedup vs baseline: 2.1563x; 1.1419x over previous
#include <cuda_runtime.h>
#include <cstdint>
#include <math.h>

#define N_Q      4096
#define N_KV     32768
#define C_DIM    256
#define KNN      100
#define THREADS  256
#define MQ       4                 // queries per CTA
#define GRID     (N_Q / MQ)
#define LN_EPS   1e-5f
#define NWORDS   (N_KV / 2)        // 16384 point-pairs
#define CAND_CAP 2048
#define QSCALE   2048.0f
#define SRANK    20                // sample rank for threshold (of 1024 samples)

struct __align__(16) SmemLayout {
    unsigned int cand[MQ][CAND_CAP];   // 32768 B: (key16<<16) | idx
    float        logits[MQ][112];
    float        wts[MQ][112];
    int          sel[MQ][128];
    int          candn[MQ];
    float        thi[MQ];
    int          qflag[MQ];
    int          redo;
    unsigned int hist[256];
    int          wsum[8];
    unsigned int bsel;
    int          krem_s;
    float        qpos[MQ][4];          // qx,qy,qz,|q|^2
    int          eq_idx[64];
    float        eq_d2[64];
    int          n_less;
    int          eq_ctr;
    float        red1[MQ][2];
    float        red2[MQ][2];
};

extern __shared__ unsigned char smem_raw[];

// Parallel 256-bin rank-select: finds bin whose cumulative count crosses krem.
// Sets s.bsel = bin, s.krem_s = krem - exclusive_prefix(bin). Block collective.
__device__ __forceinline__ void bin_select(SmemLayout& s, int krem,
                                           int tid, int lane, int wid)
{
    int c = (int)s.hist[tid];
    int x = c;
    #pragma unroll
    for (int o = 1; o < 32; o <<= 1) {
        int y = __shfl_up_sync(0xffffffffu, x, o);
        if (lane >= o) x += y;
    }
    if (lane == 31) s.wsum[wid] = x;
    __syncthreads();
    if (tid == 0) {
        int acc = 0;
        #pragma unroll
        for (int ww = 0; ww < 8; ww++) { int t = s.wsum[ww]; s.wsum[ww] = acc; acc += t; }
    }
    __syncthreads();
    int incl = x + s.wsum[wid];
    int excl = incl - c;
    if (krem > excl && krem <= incl) { s.bsel = (unsigned)tid; s.krem_s = krem - excl; }
    __syncthreads();
}

__device__ __forceinline__ unsigned quant_key(float d2)
{
    float f = fmaxf(d2, 0.0f) * QSCALE;
    unsigned k = (unsigned)f;
    return k > 65535u ? 65535u : k;
}

__global__ __launch_bounds__(THREADS)
void sparse_attn_kernel(const float* __restrict__ q_feat,
                        const float* __restrict__ k_feat,
                        const float* __restrict__ v_feat,
                        const float* __restrict__ q_pos,
                        const float* __restrict__ k_pos,
                        const float* __restrict__ gamma,
                        const float* __restrict__ beta,
                        float* __restrict__ out)
{
    SmemLayout& s = *reinterpret_cast<SmemLayout*>(smem_raw);
    const int tid   = threadIdx.x;
    const int lane  = tid & 31;
    const int wid   = tid >> 5;
    const int qbase = blockIdx.x * MQ;

    if (tid < MQ) {
        float x = q_pos[(qbase + tid) * 3 + 0];
        float y = q_pos[(qbase + tid) * 3 + 1];
        float z = q_pos[(qbase + tid) * 3 + 2];
        s.qpos[tid][0] = x; s.qpos[tid][1] = y; s.qpos[tid][2] = z;
        s.qpos[tid][3] = x * x + y * y + z * z;
        s.candn[tid] = 0; s.qflag[tid] = 1;
    }
    __syncthreads();

    float Qx[MQ], Qy[MQ], Qz[MQ], Qs[MQ];
    #pragma unroll
    for (int m = 0; m < MQ; m++) {
        Qx[m] = s.qpos[m][0]; Qy[m] = s.qpos[m][1];
        Qz[m] = s.qpos[m][2]; Qs[m] = s.qpos[m][3];
    }

    // ---- Sample pass: per-query threshold from a 1/32 stride sample ----
    float sx[4], sy[4], sz[4];
    #pragma unroll
    for (int k = 0; k < 4; k++) {
        int j = 32 * (tid + 256 * k);
        sx[k] = k_pos[3 * j + 0];
        sy[k] = k_pos[3 * j + 1];
        sz[k] = k_pos[3 * j + 2];
    }
    for (int m = 0; m < MQ; m++) {
        s.hist[tid] = 0u;
        __syncthreads();
        #pragma unroll
        for (int k = 0; k < 4; k++) {
            float d2 = Qs[m] + sx[k] * sx[k] + sy[k] * sy[k] + sz[k] * sz[k]
                     - 2.0f * (Qx[m] * sx[k] + Qy[m] * sy[k] + Qz[m] * sz[k]);
            atomicAdd(&s.hist[quant_key(d2) >> 8], 1u);
        }
        __syncthreads();
        bin_select(s, SRANK, tid, lane, wid);
        if (tid == 0)
            s.thi[m] = (float)((s.bsel + 1u) << 8) * (1.0f / QSCALE);
        __syncthreads();
    }

    bool active[MQ];
    float Thi[MQ];
    #pragma unroll
    for (int m = 0; m < MQ; m++) { active[m] = true; Thi[m] = s.thi[m]; }

    // ---- Main pass: stream k_pos once, compact candidates per query ----
    const float2* kp2 = reinterpret_cast<const float2*>(k_pos);
    for (int attempt = 0; attempt < 6; attempt++) {
        for (int w = tid; w < NWORDS; w += THREADS) {
            float2 p0 = kp2[3 * w + 0];
            float2 p1 = kp2[3 * w + 1];
            float2 p2 = kp2[3 * w + 2];
            float ax = p0.x, ay = p0.y, az = p1.x;
            float bx = p1.y, by = p2.x, bz = p2.y;
            float kka = ax * ax + ay * ay + az * az;
            float kkb = bx * bx + by * by + bz * bz;
            #pragma unroll
            for (int m = 0; m < MQ; m++) {
                if (!active[m]) continue;
                float d2a = Qs[m] + kka
                          - 2.0f * (Qx[m] * ax + Qy[m] * ay + Qz[m] * az);
                float d2b = Qs[m] + kkb
                          - 2.0f * (Qx[m] * bx + Qy[m] * by + Qz[m] * bz);
                if (d2a < Thi[m]) {
                    int p = atomicAdd(&s.candn[m], 1);
                    if (p < CAND_CAP)
                        s.cand[m][p] = (quant_key(d2a) << 16) | (unsigned)(2 * w);
                }
                if (d2b < Thi[m]) {
                    int p = atomicAdd(&s.candn[m], 1);
                    if (p < CAND_CAP)
                        s.cand[m][p] = (quant_key(d2b) << 16) | (unsigned)(2 * w + 1);
                }
            }
        }
        __syncthreads();
        if (tid == 0) s.redo = 0;
        __syncthreads();
        if (tid < MQ && s.qflag[tid]) {
            int n = s.candn[tid];
            if (n >= KNN && n <= CAND_CAP) {
                s.qflag[tid] = 0;
            } else {
                s.candn[tid] = 0;
                s.thi[tid] = (n < KNN) ? s.thi[tid] * 2.0f : s.thi[tid] * 0.5f;
                atomicExch(&s.redo, 1);
            }
        }
        __syncthreads();
        if (!s.redo) break;
        #pragma unroll
        for (int m = 0; m < MQ; m++) {
            active[m] = s.qflag[m] != 0;
            Thi[m] = s.thi[m];
        }
        __syncthreads();
    }

    // ---- Per query: exact selection (block-wide, serial over m; cheap) ----
    for (int m = 0; m < MQ; m++) {
        const int nc_raw = s.candn[m];
        const int nc = nc_raw < CAND_CAP ? nc_raw : CAND_CAP;

        // dynamic shift so candidate keys fit 256 bins
        int maxkey = (int)(s.thi[m] * QSCALE);
        if (maxkey > 65535) maxkey = 65535;
        int sh = 0;
        while ((maxkey >> sh) > 255) sh++;

        s.hist[tid] = 0u;
        if (tid == 0) { s.n_less = 0; s.eq_ctr = 0; }
        __syncthreads();
        for (int t = tid; t < nc; t += THREADS)
            atomicAdd(&s.hist[(s.cand[m][t] >> 16) >> sh], 1u);
        __syncthreads();
        bin_select(s, KNN, tid, lane, wid);
        const unsigned bsel = s.bsel;
        const int need_eq = s.krem_s;
        __syncthreads();
        for (int t = tid; t < nc; t += THREADS) {
            unsigned cw = s.cand[m][t];
            unsigned b = (cw >> 16) >> sh;
            int j = (int)(cw & 0xffffu);
            if (b < bsel) {
                s.sel[m][atomicAdd(&s.n_less, 1)] = j;
            } else if (b == bsel) {
                int p = atomicAdd(&s.eq_ctr, 1);
                if (p < 64) s.eq_idx[p] = j;
            }
        }
        __syncthreads();

        // exact fp32 resolution of the boundary bin
        int ne = s.eq_ctr; if (ne > 64) ne = 64;
        if (tid < ne) {
            int j = s.eq_idx[tid];
            float kx = k_pos[3 * j], ky = k_pos[3 * j + 1], kz = k_pos[3 * j + 2];
            float d2 = Qs[m] + kx * kx + ky * ky + kz * kz
                     - 2.0f * (Qx[m] * kx + Qy[m] * ky + Qz[m] * kz);
            s.eq_d2[tid] = fmaxf(d2, 0.0f);
        }
        __syncthreads();
        if (tid == 0) {
            int nl = s.n_less;
            int take = need_eq < ne ? need_eq : ne;
            for (int a = 0; a < take; ++a) {
                int best = a;
                for (int b = a + 1; b < ne; ++b) {
                    if (s.eq_d2[b] < s.eq_d2[best] ||
                        (s.eq_d2[b] == s.eq_d2[best] && s.eq_idx[b] < s.eq_idx[best]))
                        best = b;
                }
                float td = s.eq_d2[a]; s.eq_d2[a] = s.eq_d2[best]; s.eq_d2[best] = td;
                int   ti = s.eq_idx[a]; s.eq_idx[a] = s.eq_idx[best]; s.eq_idx[best] = ti;
                s.sel[m][nl + a] = s.eq_idx[a];
            }
        }
        __syncthreads();
    }

    // ================= Parallel epilogues: 2 warps per query =================
    const int pm    = wid >> 1;          // query 0..3 owned by this warp pair
    const int pw    = wid & 1;           // warp index within the pair
    const int ptid  = (pw << 5) | lane;  // 0..63 within the pair
    const int qi    = qbase + pm;
    const int barid = pm + 1;            // named barriers 1..4

    // q_feat held in registers: lane owns channels lane*8 .. lane*8+7
    const float4* qf4 = reinterpret_cast<const float4*>(q_feat + (size_t)qi * C_DIM);
    float4 q0 = qf4[2 * lane + 0];
    float4 q1 = qf4[2 * lane + 1];

    // ---- logits: 50 neighbors per warp ----
    for (int j = pw; j < KNN; j += 2) {
        const float4* kr = reinterpret_cast<const float4*>(
            k_feat + (size_t)s.sel[pm][j] * C_DIM);
        float4 a0 = kr[2 * lane + 0];
        float4 a1 = kr[2 * lane + 1];
        float p = a0.x * q0.x + a0.y * q0.y + a0.z * q0.z + a0.w * q0.w
                + a1.x * q1.x + a1.y * q1.y + a1.z * q1.z + a1.w * q1.w;
        #pragma unroll
        for (int o = 16; o > 0; o >>= 1)
            p += __shfl_xor_sync(0xffffffffu, p, o);
        if (lane == 0) s.logits[pm][j] = p * 0.0625f;   // C^-0.5 = 1/16
    }
    asm volatile("bar.sync %0, %1;" :: "r"(barid), "r"(64) : "memory");

    // ---- softmax normalizers (computed redundantly by each warp) ----
    float mx = -INFINITY;
    #pragma unroll
    for (int u = 0; u < 4; u++) {
        int j = lane + 32 * u;
        if (j < KNN) mx = fmaxf(mx, s.logits[pm][j]);
    }
    #pragma unroll
    for (int o = 16; o > 0; o >>= 1)
        mx = fmaxf(mx, __shfl_xor_sync(0xffffffffu, mx, o));
    float ssum = 0.0f;
    #pragma unroll
    for (int u = 0; u < 4; u++) {
        int j = lane + 32 * u;
        if (j < KNN) ssum += expf(s.logits[pm][j] - mx);
    }
    #pragma unroll
    for (int o = 16; o > 0; o >>= 1)
        ssum += __shfl_xor_sync(0xffffffffu, ssum, o);
    float inv = 1.0f / ssum;
    #pragma unroll
    for (int j = ptid; j < KNN; j += 64)
        s.wts[pm][j] = expf(s.logits[pm][j] - mx) * inv;
    asm volatile("bar.sync %0, %1;" :: "r"(barid), "r"(64) : "memory");

    // ---- weighted V gather: thread owns channels 4*ptid..4*ptid+3 ----
    float4 acc = make_float4(0.f, 0.f, 0.f, 0.f);
    const float* wt = s.wts[pm];
    const int*   sl = s.sel[pm];
    #pragma unroll 5
    for (int j = 0; j < KNN; j++) {
        float w = wt[j];
        const float4 vr = *reinterpret_cast<const float4*>(
            v_feat + (size_t)sl[j] * C_DIM + 4 * ptid);
        acc.x += w * vr.x; acc.y += w * vr.y;
        acc.z += w * vr.z; acc.w += w * vr.w;
    }

    // res.at[arange].set(x) covers every row -> y = x + x = 2x
    float4 y = make_float4(2.f * acc.x, 2.f * acc.y, 2.f * acc.z, 2.f * acc.w);

    // ---- LayerNorm over C=256 (2-warp reduction) ----
    float s1 = y.x + y.y + y.z + y.w;
    float s2 = y.x * y.x + y.y * y.y + y.z * y.z + y.w * y.w;
    #pragma unroll
    for (int o = 16; o > 0; o >>= 1) {
        s1 += __shfl_xor_sync(0xffffffffu, s1, o);
        s2 += __shfl_xor_sync(0xffffffffu, s2, o);
    }
    if (lane == 0) { s.red1[pm][pw] = s1; s.red2[pm][pw] = s2; }
    asm volatile("bar.sync %0, %1;" :: "r"(barid), "r"(64) : "memory");
    float a = s.red1[pm][0] + s.red1[pm][1];
    float b = s.red2[pm][0] + s.red2[pm][1];
    float mean = a * (1.0f / C_DIM);
    float var  = b * (1.0f / C_DIM) - mean * mean;
    float rstd = rsqrtf(var + LN_EPS);

    const float4 g  = *reinterpret_cast<const float4*>(gamma + 4 * ptid);
    const float4 be = *reinterpret_cast<const float4*>(beta  + 4 * ptid);
    float4 o4;
    o4.x = (y.x - mean) * rstd * g.x + be.x;
    o4.y = (y.y - mean) * rstd * g.y + be.y;
    o4.z = (y.z - mean) * rstd * g.z + be.z;
    o4.w = (y.w - mean) * rstd * g.w + be.w;
    *reinterpret_cast<float4*>(out + (size_t)qi * C_DIM + 4 * ptid) = o4;
}

extern "C" void kernel_launch(void* const* d_in, const int* in_sizes, int n_in,
                              void* d_out, int out_size)
{
    // inputs: 0=res_feat (dead: scatter covers all rows), 1=q_feat, 2=k_feat,
    //         3=v_feat, 4=q_pos, 5=k_pos, 6=gamma, 7=beta
    const float* q_feat = (const float*)d_in[1];
    const float* k_feat = (const float*)d_in[2];
    const float* v_feat = (const float*)d_in[3];
    const float* q_pos  = (const float*)d_in[4];
    const float* k_pos  = (const float*)d_in[5];
    const float* gamma  = (const float*)d_in[6];
    const float* beta   = (const float*)d_in[7];
    float* out = (float*)d_out;

    const int smem_bytes = (int)sizeof(SmemLayout);
    cudaFuncSetAttribute(sparse_attn_kernel,
                         cudaFuncAttributeMaxDynamicSharedMemorySize, smem_bytes);
    sparse_attn_kernel<<<GRID, THREADS, smem_bytes>>>(
        q_feat, k_feat, v_feat, q_pos, k_pos, gamma, beta, out);
}